// round 16
// baseline (speedup 1.0000x reference)
#include <cuda_runtime.h>

// Problem dims (fixed by the reference setup_inputs)
#define B_    256
#define F_    300
#define JC_   1600
#define NC_   60
#define J4_   (JC_ / 4)    // 400 float4 per frame
#define CHUNK 50           // frames per pooling tile
#define NCH   (F_ / CHUNK) // 6 chunks
#define NTILE (B_ * NCH)   // 1536 pooling tiles
#define NQ    (NC_ / 4)    // 15 n-quads
#define BTILE 16           // batch rows per fc task
#define BT_N  (B_ / BTILE) // 16 batch tiles
#define NFCT  (NQ * BT_N)  // 240 fc tasks
#define THREADS 400

// Pooled (un-normalized) feature sums [B, JC] — 1.6 MB
__device__ float    g_pooled[(size_t)B_ * JC_];
// Per-batch chunk-arrival counters (memset to 0 each launch)
__device__ unsigned g_done[B_];

__device__ __forceinline__ unsigned ld_acquire_gpu(const unsigned* p) {
    unsigned v;
    asm volatile("ld.global.acquire.gpu.u32 %0, [%1];" : "=r"(v) : "l"(p) : "memory");
    return v;
}

// ---------------------------------------------------------------------------
// Tail-fused kernel. grid = NTILE + NFCT = 1776 blocks, block = 400, occ 2.
//  bid <  1536 : pool tile (b-major: batches complete progressively).
//                Proven body: unroll-8 __ldcs + red.global.add.v4, then
//                fence + atomicAdd arrival on g_done[b].
//  bid >= 1536 : FC task, scheduled in the LAST wave (bids dispatch ~in
//                order), so it never steals residency from the main pool
//                stream (the R14 mistake). W slice -> smem immediately,
//                per-warp spin on g_done, then the proven R12 dot.
// __launch_bounds__(400, 2): 80-reg budget keeps the FC inner loop's deep
// unroll fully batched (R12's regs=64 schedule).
// ---------------------------------------------------------------------------
__global__ __launch_bounds__(THREADS, 2) void fused_kernel(
    const float* __restrict__ x,       // [B, F, JC]
    const int*   __restrict__ lengths, // [B]
    const float* __restrict__ W,       // [JC, NC] row-major
    const float* __restrict__ bias,    // [NC]
    float*       __restrict__ out)     // [B, NC]
{
    __shared__ float4 sW[JC_];         // 25.6 KB (FC role only)

    const int bid = blockIdx.x;
    const int t   = threadIdx.x;

    if (bid < NTILE) {
        // ================= Pool role =================
        const int b = bid / NCH;       // b-major
        const int c = bid - b * NCH;
        const int len = lengths[b];
        const int f0 = c * CHUNK;

        if (f0 < len) {
            const int f1 = min(f0 + CHUNK, len);
            const float4* __restrict__ xb =
                reinterpret_cast<const float4*>(x + (size_t)b * F_ * JC_);
            const int j4 = t;

            float ax = 0.f, ay = 0.f, az = 0.f, aw = 0.f;
            int f = f0;
            for (; f + 8 <= f1; f += 8) {
                float4 v0 = __ldcs(&xb[(size_t)(f + 0) * J4_ + j4]);
                float4 v1 = __ldcs(&xb[(size_t)(f + 1) * J4_ + j4]);
                float4 v2 = __ldcs(&xb[(size_t)(f + 2) * J4_ + j4]);
                float4 v3 = __ldcs(&xb[(size_t)(f + 3) * J4_ + j4]);
                float4 v4 = __ldcs(&xb[(size_t)(f + 4) * J4_ + j4]);
                float4 v5 = __ldcs(&xb[(size_t)(f + 5) * J4_ + j4]);
                float4 v6 = __ldcs(&xb[(size_t)(f + 6) * J4_ + j4]);
                float4 v7 = __ldcs(&xb[(size_t)(f + 7) * J4_ + j4]);
                ax += (v0.x + v1.x) + (v2.x + v3.x) + ((v4.x + v5.x) + (v6.x + v7.x));
                ay += (v0.y + v1.y) + (v2.y + v3.y) + ((v4.y + v5.y) + (v6.y + v7.y));
                az += (v0.z + v1.z) + (v2.z + v3.z) + ((v4.z + v5.z) + (v6.z + v7.z));
                aw += (v0.w + v1.w) + (v2.w + v3.w) + ((v4.w + v5.w) + (v6.w + v7.w));
            }
            for (; f < f1; f++) {
                float4 v = __ldcs(&xb[(size_t)f * J4_ + j4]);
                ax += v.x; ay += v.y; az += v.z; aw += v.w;
            }
            float* dst = g_pooled + (size_t)b * JC_ + j4 * 4;
            asm volatile("red.global.add.v4.f32 [%0], {%1, %2, %3, %4};"
                         :: "l"(dst), "f"(ax), "f"(ay), "f"(az), "f"(aw)
                         : "memory");
        }

        // arrival: publish reds, then count (every pool block arrives)
        __threadfence();
        __syncthreads();
        if (t == 0) atomicAdd(&g_done[b], 1u);
        return;
    }

    // ================= FC role (last wave) =================
    {
        const int task = bid - NTILE;          // 0..239
        const int q  = task % NQ;              // 0..14
        const int b0 = (task / NQ) * BTILE;    // batch tile base

        // W slice -> smem (overlaps with the pool tail on other SMs)
        const float4* __restrict__ W4 = reinterpret_cast<const float4*>(W);
#pragma unroll
        for (int j = t; j < JC_; j += THREADS)
            sW[j] = W4[(size_t)j * NQ + q];
        __syncthreads();

        if (t >= 256) return;
        const int w = t >> 5;                  // 0..7
        const int l = t & 31;
        const int bA = b0 + w;
        const int bB = b0 + w + 8;

        // per-warp spin until both batches fully pooled
        while (ld_acquire_gpu(&g_done[bA]) < (unsigned)NCH) __nanosleep(64);
        while (ld_acquire_gpu(&g_done[bB]) < (unsigned)NCH) __nanosleep(64);
        __syncwarp();

        const int lenA = lengths[bA];
        const int lenB = lengths[bB];
        const float* __restrict__ srcA = (lenA <= 1)
            ? (x + (size_t)bA * F_ * JC_) : (g_pooled + (size_t)bA * JC_);
        const float* __restrict__ srcB = (lenB <= 1)
            ? (x + (size_t)bB * F_ * JC_) : (g_pooled + (size_t)bB * JC_);
        const float invA = (lenA <= 1) ? 1.0f : 1.0f / (float)lenA;
        const float invB = (lenB <= 1) ? 1.0f : 1.0f / (float)lenB;

        float4 a0 = make_float4(0.f, 0.f, 0.f, 0.f);
        float4 a1 = a0;
#pragma unroll 10
        for (int k = 0; k < JC_ / 32; k++) {   // 50 iterations, deep batch
            const int j = k * 32 + l;
            const float pA = srcA[j];          // coalesced 128B warp load
            const float pB = srcB[j];
            const float4 wv = sW[j];           // conflict-free LDS.128
            a0.x += pA * wv.x; a0.y += pA * wv.y;
            a0.z += pA * wv.z; a0.w += pA * wv.w;
            a1.x += pB * wv.x; a1.y += pB * wv.y;
            a1.z += pB * wv.z; a1.w += pB * wv.w;
        }
#pragma unroll
        for (int off = 16; off > 0; off >>= 1) {
            a0.x += __shfl_xor_sync(0xFFFFFFFF, a0.x, off);
            a0.y += __shfl_xor_sync(0xFFFFFFFF, a0.y, off);
            a0.z += __shfl_xor_sync(0xFFFFFFFF, a0.z, off);
            a0.w += __shfl_xor_sync(0xFFFFFFFF, a0.w, off);
            a1.x += __shfl_xor_sync(0xFFFFFFFF, a1.x, off);
            a1.y += __shfl_xor_sync(0xFFFFFFFF, a1.y, off);
            a1.z += __shfl_xor_sync(0xFFFFFFFF, a1.z, off);
            a1.w += __shfl_xor_sync(0xFFFFFFFF, a1.w, off);
        }
        if (l == 0) {
            const int n = 4 * q;
            const float c0 = bias[n + 0], c1 = bias[n + 1];
            const float c2 = bias[n + 2], c3 = bias[n + 3];
            float* oA = out + (size_t)bA * NC_ + n;
            oA[0] = a0.x * invA + c0; oA[1] = a0.y * invA + c1;
            oA[2] = a0.z * invA + c2; oA[3] = a0.w * invA + c3;
            float* oB = out + (size_t)bB * NC_ + n;
            oB[0] = a1.x * invB + c0; oB[1] = a1.y * invB + c1;
            oB[2] = a1.z * invB + c2; oB[3] = a1.w * invB + c3;
        }
    }
}

extern "C" void kernel_launch(void* const* d_in, const int* in_sizes, int n_in,
                              void* d_out, int out_size)
{
    const float* x       = (const float*)d_in[0];
    const int*   lengths = (const int*)  d_in[1];
    const float* W       = (const float*)d_in[2];
    const float* bias    = (const float*)d_in[3];
    float*       out     = (float*)d_out;

    // zero accumulator + counters (graph-capturable memset nodes)
    void* pooled_ptr = nullptr;
    cudaGetSymbolAddress(&pooled_ptr, g_pooled);
    cudaMemsetAsync(pooled_ptr, 0, sizeof(float) * (size_t)B_ * JC_);
    void* done_ptr = nullptr;
    cudaGetSymbolAddress(&done_ptr, g_done);
    cudaMemsetAsync(done_ptr, 0, sizeof(unsigned) * B_);

    fused_kernel<<<NTILE + NFCT, THREADS>>>(x, lengths, W, bias, out);
}